// round 6
// baseline (speedup 1.0000x reference)
#include <cuda_runtime.h>

#define HW_   1048576   // 1024*1024
#define W_    1024
#define H_    1024
#define NTR_  12

// Output float layout (out_size = 12*4*HW + 144):
//   xs   : [0, 12*3*HW)        (12,3,1024,1024)
//   os   : [12*3*HW, 12*4*HW)  (12,1,1024,1024)
//   z    : [12*4*HW, +72)   inv_z: [+72, +144)

// One block per (row h, transform n). 256 threads; thread handles pixels
// w = p*256 + tid -> lanes contiguous. Interior fast path: both x-corners
// fetched with ONE LDG.128 per (row, channel) via an aligned quad + weight
// -quad dot product; 25% straddle case adds predicated LDG.32s.
__global__ void __launch_bounds__(256)
sample_row_kernel(const float* __restrict__ x,
                  const float* __restrict__ A,
                  float* __restrict__ out) {
    const int n   = blockIdx.y;
    const int h   = blockIdx.x;
    const int tid = threadIdx.x;

    const float t00 = __ldg(A + n*6 + 0);
    const float t01 = __ldg(A + n*6 + 1);
    const float t02 = __ldg(A + n*6 + 2);
    const float t10 = __ldg(A + n*6 + 3);
    const float t11 = __ldg(A + n*6 + 4);
    const float t12 = __ldg(A + n*6 + 5);

    // Fold z / inv_z emission into this kernel (block h==0, one thread).
    if (h == 0 && tid == 0) {
        float* z  = out + (size_t)NTR_ * 4 * HW_ + n * 6;
        float* iz = z + NTR_ * 6;
        z[0] = t00; z[1] = t01; z[2] = t02;
        z[3] = t10; z[4] = t11; z[5] = t12;
        float inv = 1.0f / (t00 * t11 - t01 * t10);
        float ia =  t11 * inv, ib = -t01 * inv;
        float ic = -t10 * inv, id =  t00 * inv;
        iz[0] = ia; iz[1] = ib; iz[2] = -(ia * t02 + ib * t12);
        iz[3] = ic; iz[4] = id; iz[5] = -(ic * t02 + id * t12);
    }

    // ix = t00*(w+0.5) + t01*(h+0.5) + cx ; iy likewise
    const float cx = 512.0f * (t02 - t00 - t01 + 1.0f) - 0.5f;
    const float cy = 512.0f * (t12 - t10 - t11 + 1.0f) - 0.5f;
    const float fh = (float)h + 0.5f;
    const float hx = fmaf(t01, fh, cx);
    const float hy = fmaf(t11, fh, cy);

    const size_t row = (size_t)h * W_;
    float* xs0 = out + (size_t)n * 3 * HW_ + row;
    float* xs1 = xs0 + HW_;
    float* xs2 = xs1 + HW_;
    float* oso = out + (size_t)NTR_ * 3 * HW_ + (size_t)n * HW_ + row;

    const int lane_base = tid & ~31;   // warp's first tid (lane-uniform)

    #pragma unroll
    for (int p = 0; p < 4; ++p) {
        const int w = p * 256 + tid;
        const float fw = (float)w + 0.5f;
        const float ix = fmaf(t00, fw, hx);
        const float iy = fmaf(t10, fw, hy);

        const float x0f = floorf(ix);
        const float y0f = floorf(iy);
        const float wx1 = ix - x0f;
        const float wy1 = iy - y0f;
        const float wx0 = 1.0f - wx1;
        const float wy0 = 1.0f - wy1;

        const int x0 = (int)x0f, y0 = (int)y0f;

        // ---- warp-uniform interior test (lane-invariant operands) ----
        const float wbA = (float)(p * 256 + lane_base) + 0.5f;
        const float wbB = wbA + 31.0f;
        const float exA = fmaf(t00, wbA, hx), exB = fmaf(t00, wbB, hx);
        const float eyA = fmaf(t10, wbA, hy), eyB = fmaf(t10, wbB, hy);
        const float xlo = fminf(exA, exB), xhi = fmaxf(exA, exB);
        const float ylo = fminf(eyA, eyB), yhi = fmaxf(eyA, eyB);
        const bool interior = (xlo >= 1.0f) & (xhi <= 1021.0f) &
                              (ylo >= 1.0f) & (yhi <= 1021.0f);

        float r0, r1, r2, ro;
        if (interior) {
            const int k  = x0 & 3;
            const int xq = x0 - k;              // 16B-aligned quad base
            const int ob = (y0 << 10) + xq;

            // Weight quad: wx0 at slot k, wx1 at slot k+1 (k==3 -> straddle)
            const float wq0 = (k == 0) ? wx0 : 0.0f;
            const float wq1 = (k == 0) ? wx1 : ((k == 1) ? wx0 : 0.0f);
            const float wq2 = (k == 1) ? wx1 : ((k == 2) ? wx0 : 0.0f);
            const float wq3 = (k == 2) ? wx1 : ((k == 3) ? wx0 : 0.0f);
            const float T0 = wq0 * wy0, T1 = wq1 * wy0, T2 = wq2 * wy0, T3 = wq3 * wy0;
            const float B0 = wq0 * wy1, B1 = wq1 * wy1, B2 = wq2 * wy1, B3 = wq3 * wy1;

            const float4* pT = (const float4*)(x + ob);
            const float4* pB = (const float4*)(x + ob + W_);
            const float4 qT0 = __ldg(pT);                const float4 qB0 = __ldg(pB);
            const float4 qT1 = __ldg(pT + HW_ / 4);      const float4 qB1 = __ldg(pB + HW_ / 4);
            const float4 qT2 = __ldg(pT + 2 * HW_ / 4);  const float4 qB2 = __ldg(pB + 2 * HW_ / 4);

            r0 = qT0.x*T0 + qT0.y*T1 + qT0.z*T2 + qT0.w*T3
               + qB0.x*B0 + qB0.y*B1 + qB0.z*B2 + qB0.w*B3;
            r1 = qT1.x*T0 + qT1.y*T1 + qT1.z*T2 + qT1.w*T3
               + qB1.x*B0 + qB1.y*B1 + qB1.z*B2 + qB1.w*B3;
            r2 = qT2.x*T0 + qT2.y*T1 + qT2.z*T2 + qT2.w*T3
               + qB2.x*B0 + qB2.y*B1 + qB2.z*B2 + qB2.w*B3;

            if (k == 3) {  // x1 = xq+4 lives in the next quad: sparse scalar adds
                const float sT = wx1 * wy0, sB = wx1 * wy1;
                const float* e = x + (y0 << 10) + x0 + 1;
                r0 += __ldg(e)          * sT + __ldg(e + W_)          * sB;
                r1 += __ldg(e + HW_)    * sT + __ldg(e + HW_ + W_)    * sB;
                r2 += __ldg(e + 2*HW_)  * sT + __ldg(e + 2*HW_ + W_)  * sB;
            }
            ro = 1.0f;
        } else {
            const float w00 = wx0 * wy0;
            const float w10 = wx1 * wy0;
            const float w01 = wx0 * wy1;
            const float w11 = wx1 * wy1;

            const int x1 = x0 + 1, y1 = y0 + 1;
            const bool vx0 = ((unsigned)x0 < (unsigned)W_);
            const bool vx1 = ((unsigned)x1 < (unsigned)W_);
            const bool vy0 = ((unsigned)y0 < (unsigned)H_);
            const bool vy1 = ((unsigned)y1 < (unsigned)H_);

            const float m00 = w00 * (float)(vx0 && vy0);
            const float m10 = w10 * (float)(vx1 && vy0);
            const float m01 = w01 * (float)(vx0 && vy1);
            const float m11 = w11 * (float)(vx1 && vy1);

            const int xc0 = min(max(x0, 0), W_ - 1);
            const int xc1 = min(max(x1, 0), W_ - 1);
            const int yc0 = min(max(y0, 0), H_ - 1);
            const int yc1 = min(max(y1, 0), H_ - 1);

            const int o00 = (yc0 << 10) + xc0;
            const int o10 = (yc0 << 10) + xc1;
            const int o01 = (yc1 << 10) + xc0;
            const int o11 = (yc1 << 10) + xc1;

            r0 = __ldg(x + o00)         * m00 + __ldg(x + o10)         * m10
               + __ldg(x + o01)         * m01 + __ldg(x + o11)         * m11;
            r1 = __ldg(x + HW_ + o00)   * m00 + __ldg(x + HW_ + o10)   * m10
               + __ldg(x + HW_ + o01)   * m01 + __ldg(x + HW_ + o11)   * m11;
            r2 = __ldg(x + 2*HW_ + o00) * m00 + __ldg(x + 2*HW_ + o10) * m10
               + __ldg(x + 2*HW_ + o01) * m01 + __ldg(x + 2*HW_ + o11) * m11;
            ro = m00 + m10 + m01 + m11;
        }

        xs0[w] = r0;
        xs1[w] = r1;
        xs2[w] = r2;
        oso[w] = ro;
    }
}

extern "C" void kernel_launch(void* const* d_in, const int* in_sizes, int n_in,
                              void* d_out, int out_size) {
    const float* x = (const float*)d_in[0];        // (1,3,1024,1024)
    const float* A = (const float*)d_in[1];        // (1,12,2,3)
    float* out = (float*)d_out;

    dim3 grid(H_, NTR_);
    sample_row_kernel<<<grid, 256>>>(x, A, out);
}

// round 7
// speedup vs baseline: 1.5764x; 1.5764x over previous
#include <cuda_runtime.h>

#define HW_   1048576   // 1024*1024
#define W_    1024
#define H_    1024
#define NTR_  12

#define SH_   52        // staged rows max
#define SPW_  56        // staged row pitch (floats) = 14 float4 quads
#define NQ_   14

// Output float layout (out_size = 12*4*HW + 144):
//   xs   : [0, 12*3*HW)        (12,3,1024,1024)
//   os   : [12*3*HW, 12*4*HW)  (12,1,1024,1024)
//   z    : [12*4*HW, +72)   inv_z: [+72, +144)

__global__ void __launch_bounds__(256)
sample_tile_kernel(const float* __restrict__ x,
                   const float* __restrict__ A,
                   float* __restrict__ out) {
    __shared__ float sm0[SH_ * SPW_];
    __shared__ float sm1[SH_ * SPW_];
    __shared__ float sm2[SH_ * SPW_];

    const int n   = blockIdx.z;
    const int w0  = blockIdx.x << 5;
    const int h0  = blockIdx.y << 5;
    const int tid = threadIdx.x;

    const float t00 = __ldg(A + n*6 + 0);
    const float t01 = __ldg(A + n*6 + 1);
    const float t02 = __ldg(A + n*6 + 2);
    const float t10 = __ldg(A + n*6 + 3);
    const float t11 = __ldg(A + n*6 + 4);
    const float t12 = __ldg(A + n*6 + 5);

    if (w0 == 0 && h0 == 0 && tid == 0) {
        float* z  = out + (size_t)NTR_ * 4 * HW_ + n * 6;
        float* iz = z + NTR_ * 6;
        z[0] = t00; z[1] = t01; z[2] = t02;
        z[3] = t10; z[4] = t11; z[5] = t12;
        float inv = 1.0f / (t00 * t11 - t01 * t10);
        float ia =  t11 * inv, ib = -t01 * inv;
        float ic = -t10 * inv, id =  t00 * inv;
        iz[0] = ia; iz[1] = ib; iz[2] = -(ia * t02 + ib * t12);
        iz[3] = ic; iz[4] = id; iz[5] = -(ic * t02 + id * t12);
    }

    const float cx = 512.0f * (t02 - t00 - t01 + 1.0f) - 0.5f;
    const float cy = 512.0f * (t12 - t10 - t11 + 1.0f) - 0.5f;

    // Tile-corner preimage bbox (affine -> extremes at corners).
    const float wlo = (float)w0 + 0.5f, whi = (float)w0 + 31.5f;
    const float hlo = (float)h0 + 0.5f, hhi = (float)h0 + 31.5f;
    const float hxl = fmaf(t01, hlo, cx), hxh = fmaf(t01, hhi, cx);
    const float hyl = fmaf(t11, hlo, cy), hyh = fmaf(t11, hhi, cy);

    const float ix00 = fmaf(t00, wlo, hxl), ix01 = fmaf(t00, wlo, hxh);
    const float ix10 = fmaf(t00, whi, hxl), ix11 = fmaf(t00, whi, hxh);
    const float iy00 = fmaf(t10, wlo, hyl), iy01 = fmaf(t10, wlo, hyh);
    const float iy10 = fmaf(t10, whi, hyl), iy11 = fmaf(t10, whi, hyh);

    const float ixmin = fminf(fminf(ix00, ix01), fminf(ix10, ix11));
    const float ixmax = fmaxf(fmaxf(ix00, ix01), fmaxf(ix10, ix11));
    const float iymin = fminf(fminf(iy00, iy01), fminf(iy10, iy11));
    const float iymax = fmaxf(fmaxf(iy00, iy01), fmaxf(iy10, iy11));

    const bool inside  = (ixmin >= 5.0f) & (ixmax <= 1018.0f) &
                         (iymin >= 5.0f) & (iymax <= 1018.0f);
    const bool outside = (ixmax < -1.002f) | (ixmin > 1024.002f) |
                         (iymax < -1.002f) | (iymin > 1024.002f);

    const int tx = tid & 31;
    const int ty = tid >> 5;

    float* xs0 = out + (size_t)n * 3 * HW_;
    float* xs1 = xs0 + HW_;
    float* xs2 = xs1 + HW_;
    float* oso = out + (size_t)NTR_ * 3 * HW_ + (size_t)n * HW_;

    if (outside) {
        #pragma unroll
        for (int k = 0; k < 4; ++k) {
            const int h = h0 + ty + (k << 3);
            const size_t o = ((size_t)h << 10) + (w0 + tx);
            xs0[o] = 0.f; xs1[o] = 0.f; xs2[o] = 0.f; oso[o] = 0.f;
        }
        return;
    }

    if (inside) {
        const int xmin = (int)floorf(ixmin) - 1;
        const int ymin = (int)floorf(iymin) - 1;
        const int xq   = xmin & ~3;                      // 16B-aligned
        int Ht = ((int)floorf(iymax) + 2) - ymin + 1;
        Ht = min(Ht, min(SH_, H_ - ymin));
        const int nq = min(NQ_, (W_ - xq) >> 2);

        // ---- stage: 16 rows x 16 quad-lanes, no bounds checks, no zero-fill
        {
            const int qi = tid & 15;
            if (qi < nq) {
                for (int r = tid >> 4; r < Ht; r += 16) {
                    const float4* src = (const float4*)(x + ((ymin + r) << 10) + xq) + qi;
                    const float4 v0 = __ldg(src);
                    const float4 v1 = __ldg(src +     HW_ / 4);
                    const float4 v2 = __ldg(src + 2 * HW_ / 4);
                    const int d = r * SPW_ + (qi << 2);
                    *(float4*)&sm0[d] = v0;
                    *(float4*)&sm1[d] = v1;
                    *(float4*)&sm2[d] = v2;
                }
            }
        }
        __syncthreads();

        const float fw = (float)(w0 + tx) + 0.5f;
        #pragma unroll
        for (int k = 0; k < 4; ++k) {
            const int h = h0 + ty + (k << 3);
            const float fh = (float)h + 0.5f;
            const float ix = fmaf(t00, fw, fmaf(t01, fh, cx));
            const float iy = fmaf(t10, fw, fmaf(t11, fh, cy));

            const float x0f = floorf(ix);
            const float y0f = floorf(iy);
            const float wx1 = ix - x0f;
            const float wy1 = iy - y0f;

            const int base = ((int)y0f - ymin) * SPW_ + ((int)x0f - xq);

            float a00 = sm0[base],        a10 = sm0[base + 1];
            float a01 = sm0[base + SPW_], a11 = sm0[base + SPW_ + 1];
            float u0 = fmaf(wx1, a10 - a00, a00);
            float u1 = fmaf(wx1, a11 - a01, a01);
            const float r0 = fmaf(wy1, u1 - u0, u0);

            a00 = sm1[base];        a10 = sm1[base + 1];
            a01 = sm1[base + SPW_]; a11 = sm1[base + SPW_ + 1];
            u0 = fmaf(wx1, a10 - a00, a00);
            u1 = fmaf(wx1, a11 - a01, a01);
            const float r1 = fmaf(wy1, u1 - u0, u0);

            a00 = sm2[base];        a10 = sm2[base + 1];
            a01 = sm2[base + SPW_]; a11 = sm2[base + SPW_ + 1];
            u0 = fmaf(wx1, a10 - a00, a00);
            u1 = fmaf(wx1, a11 - a01, a01);
            const float r2 = fmaf(wy1, u1 - u0, u0);

            const size_t o = ((size_t)h << 10) + (w0 + tx);
            xs0[o] = r0; xs1[o] = r1; xs2[o] = r2; oso[o] = 1.0f;
        }
        return;
    }

    // ---- boundary tiles: per-pixel clamp + validity path (always correct)
    const float fw = (float)(w0 + tx) + 0.5f;
    #pragma unroll
    for (int k = 0; k < 4; ++k) {
        const int h = h0 + ty + (k << 3);
        const float fh = (float)h + 0.5f;
        const float ix = fmaf(t00, fw, fmaf(t01, fh, cx));
        const float iy = fmaf(t10, fw, fmaf(t11, fh, cy));

        const float x0f = floorf(ix);
        const float y0f = floorf(iy);
        const float wx1 = ix - x0f;
        const float wy1 = iy - y0f;
        const float wx0 = 1.0f - wx1;
        const float wy0 = 1.0f - wy1;

        const int x0 = (int)x0f, y0 = (int)y0f;
        const int x1 = x0 + 1,   y1 = y0 + 1;
        const bool vx0 = ((unsigned)x0 < (unsigned)W_);
        const bool vx1 = ((unsigned)x1 < (unsigned)W_);
        const bool vy0 = ((unsigned)y0 < (unsigned)H_);
        const bool vy1 = ((unsigned)y1 < (unsigned)H_);

        const float m00 = wx0 * wy0 * (float)(vx0 && vy0);
        const float m10 = wx1 * wy0 * (float)(vx1 && vy0);
        const float m01 = wx0 * wy1 * (float)(vx0 && vy1);
        const float m11 = wx1 * wy1 * (float)(vx1 && vy1);

        const int xc0 = min(max(x0, 0), W_ - 1);
        const int xc1 = min(max(x1, 0), W_ - 1);
        const int yc0 = min(max(y0, 0), H_ - 1);
        const int yc1 = min(max(y1, 0), H_ - 1);

        const int o00 = (yc0 << 10) + xc0;
        const int o10 = (yc0 << 10) + xc1;
        const int o01 = (yc1 << 10) + xc0;
        const int o11 = (yc1 << 10) + xc1;

        const float r0 = __ldg(x + o00)         * m00 + __ldg(x + o10)         * m10
                       + __ldg(x + o01)         * m01 + __ldg(x + o11)         * m11;
        const float r1 = __ldg(x + HW_ + o00)   * m00 + __ldg(x + HW_ + o10)   * m10
                       + __ldg(x + HW_ + o01)   * m01 + __ldg(x + HW_ + o11)   * m11;
        const float r2 = __ldg(x + 2*HW_ + o00) * m00 + __ldg(x + 2*HW_ + o10) * m10
                       + __ldg(x + 2*HW_ + o01) * m01 + __ldg(x + 2*HW_ + o11) * m11;

        const size_t o = ((size_t)h << 10) + (w0 + tx);
        xs0[o] = r0; xs1[o] = r1; xs2[o] = r2;
        oso[o] = m00 + m10 + m01 + m11;
    }
}

extern "C" void kernel_launch(void* const* d_in, const int* in_sizes, int n_in,
                              void* d_out, int out_size) {
    const float* x = (const float*)d_in[0];        // (1,3,1024,1024)
    const float* A = (const float*)d_in[1];        // (1,12,2,3)
    float* out = (float*)d_out;

    dim3 grid(W_ / 32, H_ / 32, NTR_);
    sample_tile_kernel<<<grid, 256>>>(x, A, out);
}